// round 4
// baseline (speedup 1.0000x reference)
#include <cuda_runtime.h>
#include <math_constants.h>
#include <cstdint>

// Problem shape (fixed per reference):
//   cls_pred  [8, 80, 256, 256] f32
//   txty_pred [8,  2, 256, 256] f32
//   twth_pred [8,  2, 256, 256] f32
// Output: bbox[100,4], score[100], cls[100]  -> 600 f32, batch 0 only.

#define C_CLS   80
#define H_DIM   256
#define W_DIM   256
#define HW      (H_DIM * W_DIM)           // 65536
#define N_ALL   (C_CLS * HW)              // 5242880
#define TOPK_N  100

// Scratch (static device allocations are allowed)
__device__ unsigned           g_cand_key[N_ALL];
__device__ unsigned           g_cand_idx[N_ALL];
__device__ int                g_cand_count;
__device__ unsigned           g_hist[65536];

__device__ __forceinline__ unsigned long long pack_cand(unsigned key, unsigned idx) {
    // larger packed value == better: higher score first, lower idx first on ties
    return ((unsigned long long)key << 32) | (unsigned long long)(~idx);
}

// ---------------------------------------------------------------------------
// reset: zero histogram + counter
// ---------------------------------------------------------------------------
__global__ void reset_kernel() {
    int i = blockIdx.x * blockDim.x + threadIdx.x;
    if (i < 65536) g_hist[i] = 0u;
    if (i == 0)    g_cand_count = 0;
}

// ---------------------------------------------------------------------------
// peaks: per (class, 32x32 tile) block. Separable 5x5 max in smem, raw-logit
// compare (sigmoid is monotone), warp-aggregated candidate append + top16 hist.
// ---------------------------------------------------------------------------
__global__ __launch_bounds__(256, 4)
void peaks_kernel(const float* __restrict__ cls) {
    __shared__ float s [36][36];   // raw tile with 2-halo
    __shared__ float rm[36][32];   // horizontal 5-max

    const int cls_id = blockIdx.y;
    const int tile   = blockIdx.x;          // 0..63
    const int ty0    = (tile >> 3) << 5;
    const int tx0    = (tile & 7)  << 5;
    const float* base = cls + (size_t)cls_id * HW;
    const int tid = threadIdx.x;            // 256 threads

    // Load 36x36 with -inf padding (matches 'SAME' reduce_window init)
    #pragma unroll
    for (int i = tid; i < 36 * 36; i += 256) {
        int ly = i / 36, lx = i - ly * 36;
        int gy = ty0 + ly - 2, gx = tx0 + lx - 2;
        float v = -CUDART_INF_F;
        if (gy >= 0 && gy < H_DIM && gx >= 0 && gx < W_DIM)
            v = base[gy * W_DIM + gx];
        s[ly][lx] = v;
    }
    __syncthreads();

    // Row-max: rm[ly][x] = max(s[ly][x..x+4]),  x = center column - 2
    #pragma unroll
    for (int i = tid; i < 36 * 32; i += 256) {
        int ly = i >> 5, x = i & 31;
        float m = s[ly][x];
        m = fmaxf(m, s[ly][x + 1]);
        m = fmaxf(m, s[ly][x + 2]);
        m = fmaxf(m, s[ly][x + 3]);
        m = fmaxf(m, s[ly][x + 4]);
        rm[ly][x] = m;
    }
    __syncthreads();

    const int lx  = tid & 31;
    const int lyb = tid >> 5;   // 0..7

    #pragma unroll
    for (int r = 0; r < 4; r++) {
        int y = lyb + r * 8;                 // tile row 0..31
        float c = s[y + 2][lx + 2];
        float m = rm[y][lx];
        m = fmaxf(m, rm[y + 1][lx]);
        m = fmaxf(m, rm[y + 2][lx]);
        m = fmaxf(m, rm[y + 3][lx]);
        m = fmaxf(m, rm[y + 4][lx]);
        bool peak = (c >= m);                // c <= m always; equality == local max (ties kept)

        unsigned key = 0u, idx = 0u;
        if (peak) {
            float score = 1.0f / (1.0f + expf(-c));
            key = __float_as_uint(score);
            idx = ((unsigned)cls_id << 16) | ((unsigned)(ty0 + y) << 8) | (unsigned)(tx0 + lx);
            atomicAdd(&g_hist[key >> 16], 1u);   // no-return -> RED
        }

        unsigned ballot = __ballot_sync(0xFFFFFFFFu, peak);
        if (ballot) {
            int lane = tid & 31;
            int pos;
            if (lane == 0) pos = atomicAdd(&g_cand_count, __popc(ballot));
            pos = __shfl_sync(0xFFFFFFFFu, pos, 0);
            if (peak) {
                int off = __popc(ballot & ((1u << lane) - 1u));
                g_cand_key[pos + off] = key;
                g_cand_idx[pos + off] = idx;
            }
        }
    }
}

// ---------------------------------------------------------------------------
// select + decode: single block.
//  (a) suffix-scan 65536-bin hist -> boundary bin b, krem = #needed from bin b
//  (b) one scan over candidates: collect (>b) and (==b) sets
//  (c) exact select among equals (packed key|~idx order), O(100^2) rank sort
//  (d) decode 100 boxes, write output
// ---------------------------------------------------------------------------
#define EQ_CAP 2048

__global__ __launch_bounds__(1024, 1)
void select_decode_kernel(const float* __restrict__ txty,
                          const float* __restrict__ twth,
                          float* __restrict__ out) {
    __shared__ unsigned           csum[1024];
    __shared__ unsigned long long s_sel[TOPK_N];
    __shared__ unsigned long long s_eq[EQ_CAP];
    __shared__ int s_ng, s_ne, s_bin;
    __shared__ unsigned long long s_best;

    const int tid = threadIdx.x;
    const int T   = 1024;

    // (a) histogram suffix scan
    unsigned msum = 0;
    #pragma unroll 4
    for (int b = tid * 64; b < tid * 64 + 64; b++) msum += g_hist[b];
    csum[tid] = msum;
    if (tid == 0) { s_ng = 0; s_ne = 0; }
    __syncthreads();

    if (tid == 0) {
        unsigned acc = 0;
        int chunk = 1023;
        while (chunk > 0 && acc + csum[chunk] < (unsigned)TOPK_N) { acc += csum[chunk]; chunk--; }
        int b = chunk * 64 + 63;
        while (b > chunk * 64 && acc + g_hist[b] < (unsigned)TOPK_N) { acc += g_hist[b]; b--; }
        s_bin = b;
    }
    __syncthreads();

    const unsigned bin = (unsigned)s_bin;
    const int n = g_cand_count;

    // (b) collect
    for (int i = tid; i < n; i += T) {
        unsigned k = g_cand_key[i];
        unsigned t16 = k >> 16;
        if (t16 > bin) {
            int p = atomicAdd(&s_ng, 1);
            if (p < TOPK_N) s_sel[p] = pack_cand(k, g_cand_idx[i]);
        } else if (t16 == bin) {
            int p = atomicAdd(&s_ne, 1);
            if (p < EQ_CAP) s_eq[p] = pack_cand(k, g_cand_idx[i]);
        }
    }
    __syncthreads();

    const int ng   = min(s_ng, TOPK_N);   // strictly-greater count (< 100 by construction)
    const int need = TOPK_N - ng;
    const int ne   = s_ne;

    // (c) pick `need` best from boundary bin
    if (ne <= EQ_CAP) {
        for (int i = tid; i < ne; i += T) {
            unsigned long long v = s_eq[i];
            int rank = 0;
            for (int j = 0; j < ne; j++) rank += (s_eq[j] > v);
            if (rank < need) s_sel[ng + rank] = v;
        }
        __syncthreads();
    } else {
        // pathological tie fallback: iterative max-scan over all candidates
        unsigned long long last = ~0ULL;
        for (int pick = 0; pick < need; pick++) {
            if (tid == 0) s_best = 0ULL;
            __syncthreads();
            unsigned long long lb = 0ULL;
            for (int i = tid; i < n; i += T) {
                unsigned k = g_cand_key[i];
                if ((k >> 16) == bin) {
                    unsigned long long v = pack_cand(k, g_cand_idx[i]);
                    if (v < last && v > lb) lb = v;
                }
            }
            atomicMax(&s_best, lb);
            __syncthreads();
            if (tid == 0) s_sel[ng + pick] = s_best;
            last = s_best;
            __syncthreads();
        }
    }

    // (d) rank-sort the 100 and decode
    if (tid < TOPK_N) {
        unsigned long long v = s_sel[tid];
        int rank = 0;
        #pragma unroll 4
        for (int j = 0; j < TOPK_N; j++) rank += (s_sel[j] > v);

        unsigned key = (unsigned)(v >> 32);
        unsigned idx = ~(unsigned)(v & 0xFFFFFFFFull);
        float score  = __uint_as_float(key);
        int   cls_id = (int)(idx >> 16);
        int   sp     = (int)(idx & 0xFFFFu);   // y*256 + x
        int   yy     = sp >> 8;
        int   xx     = sp & 255;

        float tx = txty[sp];
        float ty = txty[HW + sp];
        float tw = twth[sp];
        float th = twth[HW + sp];

        // GS = 1.0, STRIDE = 4: xy = (grid + sigmoid(t)) * 4, wh = exp(t) * 4
        float cx = ((float)xx + 1.0f / (1.0f + expf(-tx))) * 4.0f;
        float cy = ((float)yy + 1.0f / (1.0f + expf(-ty))) * 4.0f;
        float w  = expf(tw) * 4.0f;
        float h  = expf(th) * 4.0f;

        const float inv = 1.0f / 1024.0f;
        float x1 = fminf(fmaxf((cx - 0.5f * w) * inv, 0.0f), 1.0f);
        float y1 = fminf(fmaxf((cy - 0.5f * h) * inv, 0.0f), 1.0f);
        float x2 = fminf(fmaxf((cx + 0.5f * w) * inv, 0.0f), 1.0f);
        float y2 = fminf(fmaxf((cy + 0.5f * h) * inv, 0.0f), 1.0f);

        out[rank * 4 + 0] = x1;
        out[rank * 4 + 1] = y1;
        out[rank * 4 + 2] = x2;
        out[rank * 4 + 3] = y2;
        out[400 + rank]   = score;
        out[500 + rank]   = (float)cls_id;
    }
}

// ---------------------------------------------------------------------------
extern "C" void kernel_launch(void* const* d_in, const int* in_sizes, int n_in,
                              void* d_out, int out_size) {
    const float* cls  = (const float*)d_in[0];   // [8,80,256,256]
    const float* txty = (const float*)d_in[1];   // [8,2,256,256]
    const float* twth = (const float*)d_in[2];   // [8,2,256,256]
    float* out = (float*)d_out;                  // 600 f32

    reset_kernel<<<256, 256>>>();
    peaks_kernel<<<dim3(64, C_CLS), 256>>>(cls);
    select_decode_kernel<<<1, 1024>>>(txty, twth, out);
}

// round 6
// speedup vs baseline: 1.5722x; 1.5722x over previous
#include <cuda_runtime.h>
#include <math_constants.h>
#include <cstdint>

// Problem shape (fixed per reference):
//   cls_pred  [8, 80, 256, 256] f32
//   txty_pred [8,  2, 256, 256] f32
//   twth_pred [8,  2, 256, 256] f32
// Output: bbox[100,4], score[100], cls[100]  -> 600 f32, batch 0 only.

#define C_CLS   80
#define H_DIM   256
#define W_DIM   256
#define HW      (H_DIM * W_DIM)           // 65536
#define N_ALL   (C_CLS * HW)              // 5242880
#define TOPK_N  100
#define NBINS   65536

// Scratch (static device allocations are allowed). BSS -> zero-initialized;
// select_decode_kernel restores g_hist / g_cand_count to zero at its end,
// so every kernel_launch invocation sees clean state (deterministic).
__device__ unsigned g_cand_key[N_ALL];
__device__ unsigned g_cand_idx[N_ALL];
__device__ int      g_cand_count;
__device__ unsigned g_hist[NBINS];

__device__ __forceinline__ unsigned long long pack_cand(unsigned key, unsigned idx) {
    // larger packed value == better: higher score first, lower idx first on ties
    return ((unsigned long long)key << 32) | (unsigned long long)(~idx);
}

// ---------------------------------------------------------------------------
// peaks: per (class, 32x32 tile) block. Separable 5x5 max in smem, raw-logit
// compare (sigmoid strictly monotone). Candidates staged in smem; ONE global
// atomicAdd per block (was one per warp-round -> serialized ATOMG bottleneck).
// ---------------------------------------------------------------------------
__global__ __launch_bounds__(256, 4)
void peaks_kernel(const float* __restrict__ cls) {
    __shared__ float    s [36][36];   // raw tile with 2-halo
    __shared__ float    rm[36][32];   // horizontal 5-max
    __shared__ unsigned st_key[1024]; // staging (1024 = exact worst case per tile)
    __shared__ unsigned st_idx[1024];
    __shared__ int      s_count, s_base;

    const int cls_id = blockIdx.y;
    const int tile   = blockIdx.x;          // 0..63
    const int ty0    = (tile >> 3) << 5;
    const int tx0    = (tile & 7)  << 5;
    const float* base = cls + (size_t)cls_id * HW;
    const int tid = threadIdx.x;            // 256 threads

    if (tid == 0) s_count = 0;

    // Load 36x36 with -inf padding (matches 'SAME' reduce_window init)
    #pragma unroll
    for (int k = 0; k < 6; k++) {
        int i = tid + k * 256;
        if (i < 36 * 36) {
            int ly = i / 36, lx = i - ly * 36;
            int gy = ty0 + ly - 2, gx = tx0 + lx - 2;
            float v = -CUDART_INF_F;
            if (gy >= 0 && gy < H_DIM && gx >= 0 && gx < W_DIM)
                v = base[gy * W_DIM + gx];
            s[ly][lx] = v;
        }
    }
    __syncthreads();

    // Row-max: rm[ly][x] = max(s[ly][x..x+4])
    #pragma unroll
    for (int k = 0; k < 5; k++) {
        int i = tid + k * 256;
        if (i < 36 * 32) {
            int ly = i >> 5, x = i & 31;
            float m = s[ly][x];
            m = fmaxf(m, s[ly][x + 1]);
            m = fmaxf(m, s[ly][x + 2]);
            m = fmaxf(m, s[ly][x + 3]);
            m = fmaxf(m, s[ly][x + 4]);
            rm[ly][x] = m;
        }
    }
    __syncthreads();

    const int lx   = tid & 31;
    const int lyb  = tid >> 5;   // 0..7
    const int lane = tid & 31;

    #pragma unroll
    for (int r = 0; r < 4; r++) {
        int y = lyb + r * 8;                 // tile row 0..31
        float c = s[y + 2][lx + 2];
        float m = rm[y][lx];
        m = fmaxf(m, rm[y + 1][lx]);
        m = fmaxf(m, rm[y + 2][lx]);
        m = fmaxf(m, rm[y + 3][lx]);
        m = fmaxf(m, rm[y + 4][lx]);
        bool peak = (c >= m);                // c <= m always; equality == local max

        unsigned key = 0u, idx = 0u;
        if (peak) {
            float score = 1.0f / (1.0f + expf(-c));
            key = __float_as_uint(score);
            idx = ((unsigned)cls_id << 16) | ((unsigned)(ty0 + y) << 8) | (unsigned)(tx0 + lx);
            atomicAdd(&g_hist[key >> 16], 1u);   // spread across 64K bins -> cheap RED
        }

        unsigned ballot = __ballot_sync(0xFFFFFFFFu, peak);
        if (ballot) {
            int wbase;
            if (lane == 0) wbase = atomicAdd(&s_count, __popc(ballot));  // smem atomic
            wbase = __shfl_sync(0xFFFFFFFFu, wbase, 0);
            if (peak) {
                int off = __popc(ballot & ((1u << lane) - 1u));
                st_key[wbase + off] = key;
                st_idx[wbase + off] = idx;
            }
        }
    }
    __syncthreads();

    if (tid == 0) s_base = atomicAdd(&g_cand_count, s_count);  // ONE global atomic/block
    __syncthreads();

    const int cnt = s_count, gb = s_base;
    for (int i = tid; i < cnt; i += 256) {
        g_cand_key[gb + i] = st_key[i];
        g_cand_idx[gb + i] = st_idx[i];
    }
}

// ---------------------------------------------------------------------------
// select + decode: single block, 1024 threads.
//  (1) coalesced segmented hist chunk sums (64 bins/chunk, shfl half-warp reduce)
//  (2) parallel suffix scan over 1024 chunk sums
//  (3) parallel boundary-bin refinement within the boundary chunk
//  (4) zero g_hist for next invocation (overlaps with candidate scan)
//  (5) one vectorized scan over candidates: collect (>bin) and (==bin)
//  (6) exact select among boundary equals, O(100^2) rank sort, decode, write
// ---------------------------------------------------------------------------
#define EQ_CAP 2048

__global__ __launch_bounds__(1024, 1)
void select_decode_kernel(const float* __restrict__ txty,
                          const float* __restrict__ twth,
                          float* __restrict__ out) {
    __shared__ unsigned           suf[1024];
    __shared__ unsigned           hbin[64];
    __shared__ unsigned long long s_sel[TOPK_N];
    __shared__ unsigned long long s_eq[EQ_CAP];
    __shared__ int s_ng, s_ne, s_bin, s_chunk;
    __shared__ unsigned long long s_best;

    const int tid  = threadIdx.x;
    const int T    = 1024;
    const int warp = tid >> 5;
    const int lane = tid & 31;

    // (1) chunk sums, coalesced: warp w covers bins [w*2048, (w+1)*2048)
    {
        const uint4* H4 = (const uint4*)g_hist;
        #pragma unroll
        for (int k = 0; k < 16; k++) {
            uint4 u = H4[warp * 512 + k * 32 + lane];
            unsigned p = u.x + u.y + u.z + u.w;
            p += __shfl_down_sync(0xFFFFFFFFu, p, 8, 16);
            p += __shfl_down_sync(0xFFFFFFFFu, p, 4, 16);
            p += __shfl_down_sync(0xFFFFFFFFu, p, 2, 16);
            p += __shfl_down_sync(0xFFFFFFFFu, p, 1, 16);
            if ((lane & 15) == 0)
                suf[warp * 32 + 2 * k + (lane >> 4)] = p;   // chunk sum
        }
    }
    __syncthreads();

    // (2) inclusive suffix scan: suf[c] = sum_{c' >= c} chunk[c']
    #pragma unroll
    for (int d = 1; d < 1024; d <<= 1) {
        unsigned v = (tid + d < 1024) ? suf[tid + d] : 0u;
        __syncthreads();
        suf[tid] += v;
        __syncthreads();
    }

    // find boundary chunk
    {
        unsigned nxt = (tid < 1023) ? suf[tid + 1] : 0u;
        if (suf[tid] >= (unsigned)TOPK_N && nxt < (unsigned)TOPK_N) s_chunk = tid;
        if (tid == 0 && suf[0] < (unsigned)TOPK_N) s_chunk = 0;   // degenerate guard
    }
    __syncthreads();

    const int chunk = s_chunk;
    const unsigned above_chunks = (chunk < 1023) ? suf[chunk + 1] : 0u;

    if (tid < 64) hbin[tid] = g_hist[chunk * 64 + tid];
    if (tid == 0) { s_bin = chunk * 64; s_ng = 0; s_ne = 0; }
    __syncthreads();

    // (3) refine to exact boundary bin
    if (tid < 64) {
        unsigned sl = 0;
        for (int j = tid + 1; j < 64; j++) sl += hbin[j];
        if (above_chunks + sl < (unsigned)TOPK_N &&
            above_chunks + sl + hbin[tid] >= (unsigned)TOPK_N)
            s_bin = chunk * 64 + tid;
    }
    __syncthreads();

    const unsigned bin = (unsigned)s_bin;
    const int n = g_cand_count;

    // (4) zero histogram for next invocation (all reads of g_hist are done)
    {
        uint4 z = make_uint4(0u, 0u, 0u, 0u);
        uint4* H4w = (uint4*)g_hist;
        for (int i = tid; i < NBINS / 4; i += T) H4w[i] = z;
    }

    // (5) collect strictly-greater and boundary-equal candidates
    {
        const uint4* K4 = (const uint4*)g_cand_key;
        int n4 = n >> 2;
        for (int i = tid; i < n4; i += T) {
            uint4 k4 = K4[i];
            unsigned kk[4] = {k4.x, k4.y, k4.z, k4.w};
            #pragma unroll
            for (int j = 0; j < 4; j++) {
                unsigned t16 = kk[j] >> 16;
                if (t16 >= bin) {
                    int gi = i * 4 + j;
                    if (t16 > bin) {
                        int p = atomicAdd(&s_ng, 1);
                        if (p < TOPK_N) s_sel[p] = pack_cand(kk[j], g_cand_idx[gi]);
                    } else {
                        int p = atomicAdd(&s_ne, 1);
                        if (p < EQ_CAP) s_eq[p] = pack_cand(kk[j], g_cand_idx[gi]);
                    }
                }
            }
        }
        for (int gi = (n4 << 2) + tid; gi < n; gi += T) {
            unsigned k = g_cand_key[gi];
            unsigned t16 = k >> 16;
            if (t16 > bin) {
                int p = atomicAdd(&s_ng, 1);
                if (p < TOPK_N) s_sel[p] = pack_cand(k, g_cand_idx[gi]);
            } else if (t16 == bin) {
                int p = atomicAdd(&s_ne, 1);
                if (p < EQ_CAP) s_eq[p] = pack_cand(k, g_cand_idx[gi]);
            }
        }
    }
    __syncthreads();

    if (tid == 0) g_cand_count = 0;   // restore state (all threads read n already)

    const int ng   = min(s_ng, TOPK_N);   // strictly-greater count (< 100 by construction)
    const int need = TOPK_N - ng;
    const int ne   = s_ne;

    // (6a) pick `need` best from boundary bin
    if (ne <= EQ_CAP) {
        for (int i = tid; i < ne; i += T) {
            unsigned long long v = s_eq[i];
            int rank = 0;
            for (int j = 0; j < ne; j++) rank += (s_eq[j] > v);
            if (rank < need) s_sel[ng + rank] = v;
        }
        __syncthreads();
    } else {
        // pathological tie fallback: iterative max-scan over all candidates
        unsigned long long last = ~0ULL;
        for (int pick = 0; pick < need; pick++) {
            if (tid == 0) s_best = 0ULL;
            __syncthreads();
            unsigned long long lb = 0ULL;
            for (int i = tid; i < n; i += T) {
                unsigned k = g_cand_key[i];
                if ((k >> 16) == bin) {
                    unsigned long long v = pack_cand(k, g_cand_idx[i]);
                    if (v < last && v > lb) lb = v;
                }
            }
            atomicMax(&s_best, lb);
            __syncthreads();
            if (tid == 0) s_sel[ng + pick] = s_best;
            last = s_best;
            __syncthreads();
        }
    }

    // (6b) rank-sort the 100 and decode
    if (tid < TOPK_N) {
        unsigned long long v = s_sel[tid];
        int rank = 0;
        #pragma unroll 4
        for (int j = 0; j < TOPK_N; j++) rank += (s_sel[j] > v);

        unsigned key = (unsigned)(v >> 32);
        unsigned idx = ~(unsigned)(v & 0xFFFFFFFFull);
        float score  = __uint_as_float(key);
        int   cls_id = (int)(idx >> 16);
        int   sp     = (int)(idx & 0xFFFFu);   // y*256 + x
        int   yy     = sp >> 8;
        int   xx     = sp & 255;

        float tx = txty[sp];
        float ty = txty[HW + sp];
        float tw = twth[sp];
        float th = twth[HW + sp];

        // GS = 1.0, STRIDE = 4: xy = (grid + sigmoid(t)) * 4, wh = exp(t) * 4
        float cx = ((float)xx + 1.0f / (1.0f + expf(-tx))) * 4.0f;
        float cy = ((float)yy + 1.0f / (1.0f + expf(-ty))) * 4.0f;
        float w  = expf(tw) * 4.0f;
        float h  = expf(th) * 4.0f;

        const float inv = 1.0f / 1024.0f;
        float x1 = fminf(fmaxf((cx - 0.5f * w) * inv, 0.0f), 1.0f);
        float y1 = fminf(fmaxf((cy - 0.5f * h) * inv, 0.0f), 1.0f);
        float x2 = fminf(fmaxf((cx + 0.5f * w) * inv, 0.0f), 1.0f);
        float y2 = fminf(fmaxf((cy + 0.5f * h) * inv, 0.0f), 1.0f);

        out[rank * 4 + 0] = x1;
        out[rank * 4 + 1] = y1;
        out[rank * 4 + 2] = x2;
        out[rank * 4 + 3] = y2;
        out[400 + rank]   = score;
        out[500 + rank]   = (float)cls_id;
    }
}

// ---------------------------------------------------------------------------
extern "C" void kernel_launch(void* const* d_in, const int* in_sizes, int n_in,
                              void* d_out, int out_size) {
    const float* cls  = (const float*)d_in[0];   // [8,80,256,256]
    const float* txty = (const float*)d_in[1];   // [8,2,256,256]
    const float* twth = (const float*)d_in[2];   // [8,2,256,256]
    float* out = (float*)d_out;                  // 600 f32

    peaks_kernel<<<dim3(64, C_CLS), 256>>>(cls);
    select_decode_kernel<<<1, 1024>>>(txty, twth, out);
}

// round 8
// speedup vs baseline: 6.6454x; 4.2268x over previous
#include <cuda_runtime.h>
#include <math_constants.h>
#include <cstdint>

// Problem shape (fixed per reference):
//   cls_pred  [8, 80, 256, 256] f32
//   txty_pred [8,  2, 256, 256] f32
//   twth_pred [8,  2, 256, 256] f32
// Output: bbox[100,4] | score[100] | cls[100]  -> 600 f32, batch 0 only.

#define C_CLS   80
#define H_DIM   256
#define W_DIM   256
#define HW      (H_DIM * W_DIM)       // 65536
#define N_ALL   (C_CLS * HW)          // 5242880
#define TOPK_N  100
#define THR     2.5f
#define TBASE   0xC0200000u           // order-transform of +2.5f
#define NB      4096
#define EQ_CAP  2048
#define STRIP   16
#define CAP_A   768
#define CAP_B   768

// Scratch. BSS zero-init; select_decode resets the 2 counters at its end so
// every invocation is deterministic.
__device__ unsigned long long g_candA[N_ALL];   // peaks with logit > THR
__device__ unsigned long long g_candB[N_ALL];   // remaining peaks (fallback only)
__device__ int g_cntA, g_cntB;

// Order-preserving transform: float total order -> unsigned total order.
__device__ __forceinline__ unsigned fkey(float f) {
    unsigned b = __float_as_uint(f);
    return (b & 0x80000000u) ? ~b : (b | 0x80000000u);
}
__device__ __forceinline__ float fkey_inv(unsigned k) {
    unsigned b = (k & 0x80000000u) ? (k & 0x7FFFFFFFu) : ~k;
    return __uint_as_float(b);
}
__device__ __forceinline__ unsigned binof(unsigned k) {
    if (k <= TBASE) return 0u;
    unsigned d = (k - TBASE) >> 12;
    return d > (NB - 1u) ? (NB - 1u) : d;
}

// ---------------------------------------------------------------------------
// peaks: block = (strip of 16 rows) x (class). Coalesced full-width row loads,
// vertical 5-max in registers (rolling window), horizontal 5-max via smem with
// in-block column halo. Candidates staged in smem, ONE global atomic per tier.
// ---------------------------------------------------------------------------
__global__ __launch_bounds__(256)
void peaks_kernel(const float* __restrict__ cls) {
    __shared__ float sm[STRIP][260];                    // vertical-max rows, 2-col halo
    __shared__ unsigned long long stA[CAP_A], stB[CAP_B];
    __shared__ int cA, cB, bA, bB;

    const int x     = threadIdx.x;                      // 0..255 (column)
    const int strip = blockIdx.x;                       // 0..15
    const int cid   = blockIdx.y;                       // class
    const int y0    = strip * STRIP;
    const float* __restrict__ base = cls + (size_t)cid * HW;

    if (x == 0) { cA = 0; cB = 0; }
    if (x < STRIP) {                                    // column halo = -inf
        sm[x][0] = -CUDART_INF_F;  sm[x][1]   = -CUDART_INF_F;
        sm[x][258] = -CUDART_INF_F; sm[x][259] = -CUDART_INF_F;
    }

    // Rolling 5-row window: load rows y0-2 .. y0+17, emit vertical max + center.
    float win[5];
    float ctr[STRIP];
    #pragma unroll
    for (int j = 0; j < STRIP + 4; j++) {
        int gy = y0 - 2 + j;
        float v = (gy >= 0 && gy < H_DIM) ? __ldg(base + gy * W_DIM + x)
                                          : -CUDART_INF_F;
        win[j % 5] = v;                                 // static index (full unroll)
        if (j >= 2 && j < STRIP + 2) ctr[j - 2] = v;
        if (j >= 4) {
            float m = fmaxf(fmaxf(fmaxf(win[0], win[1]), fmaxf(win[2], win[3])), win[4]);
            sm[j - 4][x + 2] = m;
        }
    }
    __syncthreads();

    const int lane = x & 31;
    #pragma unroll
    for (int j = 0; j < STRIP; j++) {
        float c = ctr[j];
        float m = fmaxf(fmaxf(fmaxf(sm[j][x], sm[j][x + 1]),
                              fmaxf(sm[j][x + 2], sm[j][x + 3])), sm[j][x + 4]);
        bool peak = (c >= m);           // c <= m always; equality == local max (ties kept)
        bool isA  = peak && (c > THR);
        bool isB  = peak && !isA;

        unsigned long long cand = 0ULL;
        if (peak) {
            unsigned idx = ((unsigned)cid << 16) | ((unsigned)(y0 + j) << 8) | (unsigned)x;
            cand = ((unsigned long long)fkey(c) << 32) | (unsigned long long)(~idx);
        }

        unsigned ba = __ballot_sync(0xFFFFFFFFu, isA);
        if (ba) {
            int p;
            if (lane == 0) p = atomicAdd(&cA, __popc(ba));
            p = __shfl_sync(0xFFFFFFFFu, p, 0);
            if (isA) {
                int o = p + __popc(ba & ((1u << lane) - 1u));
                if (o < CAP_A) stA[o] = cand;
                else { int gp = atomicAdd(&g_cntA, 1); g_candA[gp] = cand; }  // rare
            }
        }
        unsigned bb = __ballot_sync(0xFFFFFFFFu, isB);
        if (bb) {
            int p;
            if (lane == 0) p = atomicAdd(&cB, __popc(bb));
            p = __shfl_sync(0xFFFFFFFFu, p, 0);
            if (isB) {
                int o = p + __popc(bb & ((1u << lane) - 1u));
                if (o < CAP_B) stB[o] = cand;
                else { int gp = atomicAdd(&g_cntB, 1); g_candB[gp] = cand; }  // rare
            }
        }
    }
    __syncthreads();

    int nA = min(cA, CAP_A), nB = min(cB, CAP_B);
    if (x == 0) bA = atomicAdd(&g_cntA, nA);
    if (x == 1) bB = atomicAdd(&g_cntB, nB);
    __syncthreads();
    for (int i = x; i < nA; i += 256) g_candA[bA + i] = stA[i];
    for (int i = x; i < nB; i += 256) g_candB[bB + i] = stB[i];
}

// ---------------------------------------------------------------------------
// select + decode: single block, 1024 threads, smem 4096-bin histogram.
// ---------------------------------------------------------------------------
__global__ __launch_bounds__(1024)
void select_decode_kernel(const float* __restrict__ txty,
                          const float* __restrict__ twth,
                          float* __restrict__ out) {
    __shared__ unsigned           hist[NB];
    __shared__ unsigned           ts[1024];
    __shared__ unsigned long long s_sel[TOPK_N];
    __shared__ unsigned long long s_eq[EQ_CAP];
    __shared__ int s_ng, s_ne, s_bin;
    __shared__ unsigned long long s_best;

    const int tid = threadIdx.x;
    const int T   = 1024;

    hist[tid] = 0u; hist[tid + 1024] = 0u; hist[tid + 2048] = 0u; hist[tid + 3072] = 0u;
    if (tid == 0) { s_ng = 0; s_ne = 0; s_bin = 0; }
    __syncthreads();

    const int  nA = g_cntA, nB = g_cntB;
    const bool fb = (nA < TOPK_N);   // exactness fallback: include tier B

    // (1) histogram
    #pragma unroll 4
    for (int i = tid; i < nA; i += T)
        atomicAdd(&hist[binof((unsigned)(g_candA[i] >> 32))], 1u);
    if (fb) {
        for (int i = tid; i < nB; i += T)
            atomicAdd(&hist[binof((unsigned)(g_candB[i] >> 32))], 1u);
    }
    __syncthreads();

    // (2) suffix scan over 1024 chunk sums (4 bins/chunk)
    ts[tid] = hist[tid * 4] + hist[tid * 4 + 1] + hist[tid * 4 + 2] + hist[tid * 4 + 3];
    __syncthreads();
    #pragma unroll
    for (int d = 1; d < 1024; d <<= 1) {
        unsigned v = (tid + d < 1024) ? ts[tid + d] : 0u;
        __syncthreads();
        ts[tid] += v;
        __syncthreads();
    }
    // (3) boundary chunk + in-chunk refinement
    {
        unsigned nxt = (tid < 1023) ? ts[tid + 1] : 0u;
        if (ts[tid] >= (unsigned)TOPK_N && nxt < (unsigned)TOPK_N) {
            unsigned acc = nxt;
            int b = tid * 4 + 3;
            while (b > tid * 4 && acc + hist[b] < (unsigned)TOPK_N) { acc += hist[b]; b--; }
            s_bin = b;
        }
    }
    __syncthreads();
    const unsigned bin = (unsigned)s_bin;

    // (4) collect strictly-greater-bin and equal-bin candidates
    #pragma unroll 4
    for (int i = tid; i < nA; i += T) {
        unsigned long long v = g_candA[i];
        unsigned b = binof((unsigned)(v >> 32));
        if (b > bin) {
            int p = atomicAdd(&s_ng, 1);
            if (p < TOPK_N) s_sel[p] = v;
        } else if (b == bin) {
            int p = atomicAdd(&s_ne, 1);
            if (p < EQ_CAP) s_eq[p] = v;
        }
    }
    if (fb) {
        for (int i = tid; i < nB; i += T) {
            unsigned long long v = g_candB[i];
            unsigned b = binof((unsigned)(v >> 32));
            if (b > bin) {
                int p = atomicAdd(&s_ng, 1);
                if (p < TOPK_N) s_sel[p] = v;
            } else if (b == bin) {
                int p = atomicAdd(&s_ne, 1);
                if (p < EQ_CAP) s_eq[p] = v;
            }
        }
    }
    __syncthreads();

    if (tid == 0) { g_cntA = 0; g_cntB = 0; }   // restore state

    const int ng   = min(s_ng, TOPK_N);         // < 100 by construction of bin
    const int need = TOPK_N - ng;
    const int ne   = s_ne;

    // (5) exact select among boundary-bin equals
    if (ne <= EQ_CAP) {
        for (int i = tid; i < ne; i += T) {
            unsigned long long v = s_eq[i];
            int rank = 0;
            for (int j = 0; j < ne; j++) rank += (s_eq[j] > v);
            if (rank < need) s_sel[ng + rank] = v;
        }
        __syncthreads();
    } else {
        // pathological tie fallback: iterative max-scan
        unsigned long long last = ~0ULL;
        for (int pick = 0; pick < need; pick++) {
            if (tid == 0) s_best = 0ULL;
            __syncthreads();
            unsigned long long lb = 0ULL;
            for (int i = tid; i < nA; i += T) {
                unsigned long long v = g_candA[i];
                if (binof((unsigned)(v >> 32)) == bin && v < last && v > lb) lb = v;
            }
            if (fb) for (int i = tid; i < nB; i += T) {
                unsigned long long v = g_candB[i];
                if (binof((unsigned)(v >> 32)) == bin && v < last && v > lb) lb = v;
            }
            atomicMax(&s_best, lb);
            __syncthreads();
            if (tid == 0) s_sel[ng + pick] = s_best;
            last = s_best;
            __syncthreads();
        }
    }

    // (6) rank-sort the 100, decode boxes, write output
    if (tid < TOPK_N) {
        unsigned long long v = s_sel[tid];
        int rank = 0;
        #pragma unroll 4
        for (int j = 0; j < TOPK_N; j++) rank += (s_sel[j] > v);

        unsigned key = (unsigned)(v >> 32);
        unsigned idx = ~(unsigned)(v & 0xFFFFFFFFull);
        float raw    = fkey_inv(key);
        float score  = 1.0f / (1.0f + expf(-raw));
        int   cls_id = (int)(idx >> 16);
        int   sp     = (int)(idx & 0xFFFFu);     // y*256 + x
        int   yy     = sp >> 8;
        int   xx     = sp & 255;

        float tx = txty[sp];
        float ty = txty[HW + sp];
        float tw = twth[sp];
        float th = twth[HW + sp];

        // GS=1, STRIDE=4: xy = (grid + sigmoid(t)) * 4, wh = exp(t) * 4
        float cx = ((float)xx + 1.0f / (1.0f + expf(-tx))) * 4.0f;
        float cy = ((float)yy + 1.0f / (1.0f + expf(-ty))) * 4.0f;
        float w  = expf(tw) * 4.0f;
        float h  = expf(th) * 4.0f;

        const float inv = 1.0f / 1024.0f;
        float x1 = fminf(fmaxf((cx - 0.5f * w) * inv, 0.0f), 1.0f);
        float y1 = fminf(fmaxf((cy - 0.5f * h) * inv, 0.0f), 1.0f);
        float x2 = fminf(fmaxf((cx + 0.5f * w) * inv, 0.0f), 1.0f);
        float y2 = fminf(fmaxf((cy + 0.5f * h) * inv, 0.0f), 1.0f);

        out[rank * 4 + 0] = x1;
        out[rank * 4 + 1] = y1;
        out[rank * 4 + 2] = x2;
        out[rank * 4 + 3] = y2;
        out[400 + rank]   = score;
        out[500 + rank]   = (float)cls_id;
    }
}

// ---------------------------------------------------------------------------
extern "C" void kernel_launch(void* const* d_in, const int* in_sizes, int n_in,
                              void* d_out, int out_size) {
    const float* cls  = (const float*)d_in[0];   // [8,80,256,256]
    const float* txty = (const float*)d_in[1];   // [8,2,256,256]
    const float* twth = (const float*)d_in[2];   // [8,2,256,256]
    float* out = (float*)d_out;                  // 600 f32

    peaks_kernel<<<dim3(H_DIM / STRIP, C_CLS), 256>>>(cls);
    select_decode_kernel<<<1, 1024>>>(txty, twth, out);
}

// round 9
// speedup vs baseline: 11.4465x; 1.7225x over previous
#include <cuda_runtime.h>
#include <math_constants.h>
#include <cstdint>

// Problem shape (fixed per reference):
//   cls_pred  [8, 80, 256, 256] f32
//   txty_pred [8,  2, 256, 256] f32
//   twth_pred [8,  2, 256, 256] f32
// Output: bbox[100,4] | score[100] | cls[100]  -> 600 f32, batch 0 only.
//
// Exact algorithm: top-100 of suppressed scores == top-100 over 5x5-local-max
// peaks (non-peaks score 0). Raw logits compared (sigmoid strictly monotone).
// Tier-A = peaks with logit > THR. If nA >= 100 the 100th-best peak > THR,
// so the true top-100 is a subset of tier-A (checked at runtime). Otherwise a
// slow exact full-rescan fallback runs inside the same kernel (never taken
// for this data: E[nA] ~ 380, P(nA<100) ~ 1e-40).

#define C_CLS   80
#define H_DIM   256
#define W_DIM   256
#define HW      (H_DIM * W_DIM)       // 65536
#define N_ALL   (C_CLS * HW)          // 5242880
#define TOPK_N  100
#define THR     3.8f
#define STRIP   16
#define SEL_CAP 2048
#define A_GCAP  65536

// Scratch. BSS zero-init; the selecting block resets counters at the end of
// every invocation, so each kernel_launch call is deterministic.
__device__ unsigned long long g_candA[A_GCAP];
__device__ unsigned long long g_candB[N_ALL];   // fallback only
__device__ int g_cntA, g_cntB, g_done;
__device__ unsigned g_hist4k[4096];             // fallback only

// Order-preserving float -> unsigned transform.
__device__ __forceinline__ unsigned fkey(float f) {
    unsigned b = __float_as_uint(f);
    return (b & 0x80000000u) ? ~b : (b | 0x80000000u);
}
__device__ __forceinline__ float fkey_inv(unsigned k) {
    unsigned b = (k & 0x80000000u) ? (k & 0x7FFFFFFFu) : ~k;
    return __uint_as_float(b);
}

__global__ __launch_bounds__(256)
void det_kernel(const float* __restrict__ cls,
                const float* __restrict__ txty,
                const float* __restrict__ twth,
                float* __restrict__ out) {
    __shared__ union {
        float              sm[STRIP][260];   // vertical-max rows + 2-col halo
        unsigned long long cand[SEL_CAP];    // select phase (last block only)
        unsigned           hist[4096];       // fallback select scratch
    } u;
    __shared__ unsigned long long s_sel[TOPK_N];
    __shared__ unsigned long long s_best;
    __shared__ int s_last, s_ng, s_bin;

    const int x     = threadIdx.x;           // column 0..255
    const int strip = blockIdx.x;             // 0..15
    const int cid   = blockIdx.y;             // class
    const int y0    = strip * STRIP;
    const int lane  = x & 31;
    const float* __restrict__ base = cls + (size_t)cid * HW;

    if (x < STRIP) {                          // column halo = -inf
        u.sm[x][0]   = -CUDART_INF_F; u.sm[x][1]   = -CUDART_INF_F;
        u.sm[x][258] = -CUDART_INF_F; u.sm[x][259] = -CUDART_INF_F;
    }

    // ---- phase 1: coalesced rolling 5-row vertical max ----
    float win[5];
    float ctr[STRIP];
    #pragma unroll
    for (int j = 0; j < STRIP + 4; j++) {
        int gy = y0 - 2 + j;
        float v = (gy >= 0 && gy < H_DIM) ? __ldg(base + gy * W_DIM + x)
                                          : -CUDART_INF_F;
        win[j % 5] = v;
        if (j >= 2 && j < STRIP + 2) ctr[j - 2] = v;
        if (j >= 4)
            u.sm[j - 4][x + 2] =
                fmaxf(fmaxf(fmaxf(win[0], win[1]), fmaxf(win[2], win[3])), win[4]);
    }
    __syncthreads();

    // ---- phase 2: gated horizontal max + warp-aggregated append ----
    #pragma unroll
    for (int j = 0; j < STRIP; j++) {
        float c = ctr[j];
        unsigned g = __ballot_sync(0xFFFFFFFFu, c > THR);   // ~0.3% of warp-rows hit
        if (g) {
            float m = fmaxf(fmaxf(fmaxf(u.sm[j][x], u.sm[j][x + 1]),
                                  fmaxf(u.sm[j][x + 2], u.sm[j][x + 3])),
                            u.sm[j][x + 4]);
            bool isA = (c > THR) && (c >= m);   // equality == local max (ties kept)
            unsigned ba = __ballot_sync(0xFFFFFFFFu, isA);
            if (ba) {
                int p;
                if (lane == 0) p = atomicAdd(&g_cntA, __popc(ba));
                p = __shfl_sync(0xFFFFFFFFu, p, 0);
                if (isA) {
                    int o = p + __popc(ba & ((1u << lane) - 1u));
                    if (o < A_GCAP) {
                        unsigned idx = ((unsigned)cid << 16) |
                                       ((unsigned)(y0 + j) << 8) | (unsigned)x;
                        g_candA[o] = ((unsigned long long)fkey(c) << 32) |
                                     (unsigned long long)(~idx);
                    }
                }
            }
        }
    }

    // ---- last-block-done ticket ----
    __syncthreads();
    if (x == 0) {
        __threadfence();
        int total = gridDim.x * gridDim.y;
        s_last = (atomicAdd(&g_done, 1) == total - 1) ? 1 : 0;
    }
    __syncthreads();
    if (!s_last) return;
    __threadfence();

    const int n = g_cntA;

    if (n >= TOPK_N && n <= SEL_CAP) {
        // ---- fast exact path: O(n^2/256) rank select over ~380 candidates ----
        for (int i = x; i < n; i += 256) u.cand[i] = g_candA[i];
        __syncthreads();
        for (int i = x; i < n; i += 256) {
            unsigned long long v = u.cand[i];
            int rank = 0;
            for (int j = 0; j < n; j++) rank += (u.cand[j] > v);
            if (rank < TOPK_N) s_sel[rank] = v;
        }
        __syncthreads();
        if (x == 0) { g_cntA = 0; g_done = 0; }
    } else {
        // ---- slow exact fallback (never taken for benchmark data) ----
        // Full rescan: all peaks, no threshold, direct 5x5 neighborhood max.
        for (int c2 = 0; c2 < C_CLS; c2++) {
            const float* b = cls + (size_t)c2 * HW;
            for (int i = x; i < HW; i += 256) {
                int yy = i >> 8, xx = i & 255;
                float c = b[i];
                float m = -CUDART_INF_F;
                for (int dy = -2; dy <= 2; dy++) {
                    int ny = yy + dy;
                    if (ny < 0 || ny >= H_DIM) continue;
                    for (int dx = -2; dx <= 2; dx++) {
                        int nx = xx + dx;
                        if (nx < 0 || nx >= W_DIM) continue;
                        m = fmaxf(m, b[ny * W_DIM + nx]);
                    }
                }
                bool peak = (c >= m);
                unsigned ball = __ballot_sync(0xFFFFFFFFu, peak);
                if (ball) {
                    int p;
                    if (lane == 0) p = atomicAdd(&g_cntB, __popc(ball));
                    p = __shfl_sync(0xFFFFFFFFu, p, 0);
                    if (peak) {
                        unsigned idx = ((unsigned)c2 << 16) | (unsigned)i;
                        g_candB[p + __popc(ball & ((1u << lane) - 1u))] =
                            ((unsigned long long)fkey(c) << 32) |
                            (unsigned long long)(~idx);
                    }
                }
            }
        }
        __syncthreads();
        const int nb = g_cntB;

        for (int i = x; i < 4096; i += 256) g_hist4k[i] = 0u;
        __syncthreads();
        for (int i = x; i < nb; i += 256)
            atomicAdd(&g_hist4k[(unsigned)(g_candB[i] >> 52)], 1u);
        __syncthreads();
        for (int i = x; i < 4096; i += 256) u.hist[i] = g_hist4k[i];
        if (x == 0) s_ng = 0;
        __syncthreads();
        if (x == 0) {
            unsigned acc = 0; int b = 4095;
            while (b > 0 && acc + u.hist[b] < (unsigned)TOPK_N) { acc += u.hist[b]; b--; }
            s_bin = b;
        }
        __syncthreads();
        const unsigned bin = (unsigned)s_bin;

        for (int i = x; i < nb; i += 256) {
            unsigned long long v = g_candB[i];
            if ((unsigned)(v >> 52) > bin) {
                int p = atomicAdd(&s_ng, 1);
                if (p < TOPK_N) s_sel[p] = v;   // strictly-greater count < 100
            }
        }
        __syncthreads();
        int ng = min(s_ng, TOPK_N), need = TOPK_N - ng;
        unsigned long long last = ~0ULL;
        for (int pick = 0; pick < need; pick++) {
            if (x == 0) s_best = 0ULL;
            __syncthreads();
            unsigned long long lb = 0ULL;
            for (int i = x; i < nb; i += 256) {
                unsigned long long v = g_candB[i];
                if ((unsigned)(v >> 52) == bin && v < last && v > lb) lb = v;
            }
            atomicMax(&s_best, lb);
            __syncthreads();
            if (x == 0) s_sel[ng + pick] = s_best;
            last = s_best;
            __syncthreads();
        }
        if (x == 0) { g_cntA = 0; g_cntB = 0; g_done = 0; }
    }
    __syncthreads();

    // ---- decode + write (rank-sort is idempotent if already sorted) ----
    if (x < TOPK_N) {
        unsigned long long v = s_sel[x];
        int rank = 0;
        #pragma unroll 4
        for (int j = 0; j < TOPK_N; j++) rank += (s_sel[j] > v);

        unsigned key = (unsigned)(v >> 32);
        unsigned idx = ~(unsigned)(v & 0xFFFFFFFFull);
        float raw    = fkey_inv(key);
        float score  = 1.0f / (1.0f + expf(-raw));
        int   cls_id = (int)(idx >> 16);
        int   sp     = (int)(idx & 0xFFFFu);     // y*256 + x
        int   yy     = sp >> 8;
        int   xx     = sp & 255;

        float tx = txty[sp];
        float ty = txty[HW + sp];
        float tw = twth[sp];
        float th = twth[HW + sp];

        // GS=1, STRIDE=4: xy = (grid + sigmoid(t)) * 4, wh = exp(t) * 4
        float cx = ((float)xx + 1.0f / (1.0f + expf(-tx))) * 4.0f;
        float cy = ((float)yy + 1.0f / (1.0f + expf(-ty))) * 4.0f;
        float w  = expf(tw) * 4.0f;
        float h  = expf(th) * 4.0f;

        const float inv = 1.0f / 1024.0f;
        float x1 = fminf(fmaxf((cx - 0.5f * w) * inv, 0.0f), 1.0f);
        float y1 = fminf(fmaxf((cy - 0.5f * h) * inv, 0.0f), 1.0f);
        float x2 = fminf(fmaxf((cx + 0.5f * w) * inv, 0.0f), 1.0f);
        float y2 = fminf(fmaxf((cy + 0.5f * h) * inv, 0.0f), 1.0f);

        out[rank * 4 + 0] = x1;
        out[rank * 4 + 1] = y1;
        out[rank * 4 + 2] = x2;
        out[rank * 4 + 3] = y2;
        out[400 + rank]   = score;
        out[500 + rank]   = (float)cls_id;
    }
}

// ---------------------------------------------------------------------------
extern "C" void kernel_launch(void* const* d_in, const int* in_sizes, int n_in,
                              void* d_out, int out_size) {
    const float* cls  = (const float*)d_in[0];   // [8,80,256,256]
    const float* txty = (const float*)d_in[1];   // [8,2,256,256]
    const float* twth = (const float*)d_in[2];   // [8,2,256,256]
    float* out = (float*)d_out;                  // 600 f32

    det_kernel<<<dim3(H_DIM / STRIP, C_CLS), 256>>>(cls, txty, twth, out);
}